// round 14
// baseline (speedup 1.0000x reference)
#include <cuda_runtime.h>
#include <cuda_bf16.h>
#include <math.h>
#include <stdint.h>

#define D_MODEL 1024
#define N_HEADS 16
#define HEAD_DIM 64
#define BATCH 4
#define SEQ 2048
#define M_TOK (BATCH * SEQ) /* 8192 */

typedef __nv_bfloat16 bf16;

#define NELEM ((size_t)M_TOK * D_MODEL)

// ---------------- scratch (allocation-free: __device__ globals) ----------------
__device__ bf16 g_xt_hi[NELEM], g_xt_lo[NELEM];
__device__ bf16 g_xf_hi[NELEM], g_xf_lo[NELEM];
__device__ bf16 g_q1h[NELEM], g_q1l[NELEM], g_k1h[NELEM], g_k1l[NELEM], g_v1h[NELEM], g_v1l[NELEM];
__device__ bf16 g_q2h[NELEM], g_q2l[NELEM], g_k2h[NELEM], g_k2l[NELEM], g_v2h[NELEM], g_v2l[NELEM];
__device__ bf16 g_a1h[NELEM], g_a1l[NELEM], g_a2h[NELEM], g_a2l[NELEM];
__device__ bf16 g_cat_hi[2 * NELEM], g_cat_lo[2 * NELEM];
__device__ float g_t1[NELEM], g_t2[NELEM];
__device__ bf16 g_wp_hi[11u * 1024u * 1024u];
__device__ bf16 g_wp_lo[11u * 1024u * 1024u];

#define WOFF_QT 0u
#define WOFF_KT (1u * 1048576u)
#define WOFF_VT (2u * 1048576u)
#define WOFF_QF (3u * 1048576u)
#define WOFF_KF (4u * 1048576u)
#define WOFF_VF (5u * 1048576u)
#define WOFF_OT (6u * 1048576u)
#define WOFF_OF (7u * 1048576u)
#define WOFF_F2 (8u * 1048576u)
#define WOFF_F1 (9u * 1048576u)

// ---------------- helpers ----------------
__device__ __forceinline__ void split_pk(float a, float b, unsigned &hi, unsigned &lo) {
    bf16 ah = __float2bfloat16_rn(a);
    bf16 bh = __float2bfloat16_rn(b);
    hi = ((unsigned)__bfloat16_as_ushort(bh) << 16) | (unsigned)__bfloat16_as_ushort(ah);
    float ar = a - __bfloat162float(ah);
    float br = b - __bfloat162float(bh);
    lo = ((unsigned)__bfloat16_as_ushort(__float2bfloat16_rn(br)) << 16) |
         (unsigned)__bfloat16_as_ushort(__float2bfloat16_rn(ar));
}

__device__ __forceinline__ void mma16816(float* d, unsigned a0, unsigned a1,
                                         unsigned a2, unsigned a3,
                                         unsigned b0, unsigned b1) {
    asm volatile(
        "mma.sync.aligned.m16n8k16.row.col.f32.bf16.bf16.f32 "
        "{%0,%1,%2,%3},{%4,%5,%6,%7},{%8,%9},{%0,%1,%2,%3};"
        : "+f"(d[0]), "+f"(d[1]), "+f"(d[2]), "+f"(d[3])
        : "r"(a0), "r"(a1), "r"(a2), "r"(a3), "r"(b0), "r"(b1));
}

__device__ __forceinline__ unsigned saddr(const void* p) {
    return (unsigned)__cvta_generic_to_shared(p);
}
__device__ __forceinline__ void ldsm_x4(unsigned &r0, unsigned &r1, unsigned &r2,
                                        unsigned &r3, unsigned a) {
    asm volatile("ldmatrix.sync.aligned.m8n8.x4.shared.b16 {%0,%1,%2,%3},[%4];"
                 : "=r"(r0), "=r"(r1), "=r"(r2), "=r"(r3) : "r"(a));
}
__device__ __forceinline__ void ldsm_x4_t(unsigned &r0, unsigned &r1, unsigned &r2,
                                          unsigned &r3, unsigned a) {
    asm volatile("ldmatrix.sync.aligned.m8n8.x4.trans.shared.b16 {%0,%1,%2,%3},[%4];"
                 : "=r"(r0), "=r"(r1), "=r"(r2), "=r"(r3) : "r"(a));
}
__device__ __forceinline__ void cp16(unsigned dst, const void* src) {
    asm volatile("cp.async.cg.shared.global [%0], [%1], 16;" :: "r"(dst), "l"(src));
}
__device__ __forceinline__ void cp_commit() {
    asm volatile("cp.async.commit_group;");
}
__device__ __forceinline__ void cp_wait1() {
    asm volatile("cp.async.wait_group 1;" ::: "memory");
}

// ---------------- converters ----------------
__global__ __launch_bounds__(256) void split_kernel(
    const float* __restrict__ in, bf16* __restrict__ hi, bf16* __restrict__ lo)
{
    const size_t i = (size_t)blockIdx.x * 256 + threadIdx.x;
    float4 v = ((const float4*)in)[i];
    unsigned h0, l0, h1, l1;
    split_pk(v.x, v.y, h0, l0);
    split_pk(v.z, v.w, h1, l1);
    uint2 hh; hh.x = h0; hh.y = h1;
    uint2 ll; ll.x = l0; ll.y = l1;
    ((uint2*)hi)[i] = hh;
    ((uint2*)lo)[i] = ll;
}

// W[K][N] fp32 -> T[N][K] split bf16
__global__ __launch_bounds__(256) void wconv(
    const float* __restrict__ W, bf16* __restrict__ Thi, bf16* __restrict__ Tlo,
    int K, int N)
{
    __shared__ float tile[32][33];
    const int tx = threadIdx.x, ty = threadIdx.y;
    const int n0 = blockIdx.x * 32;
    const int k0 = blockIdx.y * 32;
#pragma unroll
    for (int i = 0; i < 4; i++)
        tile[ty + 8 * i][tx] = W[(size_t)(k0 + ty + 8 * i) * N + n0 + tx];
    __syncthreads();
#pragma unroll
    for (int i = 0; i < 4; i++) {
        float v = tile[tx][ty + 8 * i];
        bf16 h = __float2bfloat16_rn(v);
        const size_t o = (size_t)(n0 + ty + 8 * i) * K + k0 + tx;
        Thi[o] = h;
        Tlo[o] = __float2bfloat16_rn(v - __bfloat162float(h));
    }
}

// ---------------- shared GEMM mainloop: 128x128 tile, 4 warps of 64x64 ------------
// blockDim = 128. ldsm:MMA = 1:6.
#define TG_STAGE 40960
#define TG_SMEM (2 * TG_STAGE)
__device__ __forceinline__ void gemm_mainloop(
    const bf16* __restrict__ Ahi, const bf16* __restrict__ Alo,
    const bf16* __restrict__ Bhi, const bf16* __restrict__ Blo,
    int brow, int browB, int K, char* smem_raw, float acc[4][8][4])
{
    const int tid = threadIdx.x;
    const int lane = tid & 31;
    const int wid = tid >> 5;
    const int warpM = wid & 1;    // 2 x 64 rows
    const int warpN = wid >> 1;   // 2 x 64 cols
    const unsigned sb = saddr(smem_raw);
    const int nchunk = K >> 5;

#pragma unroll
    for (int mt = 0; mt < 4; mt++)
#pragma unroll
        for (int nt = 0; nt < 8; nt++)
#pragma unroll
            for (int i = 0; i < 4; i++) acc[mt][nt][i] = 0.0f;

    auto load_stage = [&](int c) {
        const unsigned stg = sb + (c & 1) * TG_STAGE;
        const int k0 = c * 32;
        const int r = tid;                       // 0..127 rows
        const size_t goA = (size_t)(brow + r) * K + k0;
        const size_t goB = (size_t)(browB + r) * K + k0;
#pragma unroll
        for (int q = 0; q < 4; q++) {
            const unsigned so = (unsigned)(r * 80 + q * 16);
            cp16(stg + so,          Ahi + goA + q * 8);
            cp16(stg + 10240 + so,  Alo + goA + q * 8);
            cp16(stg + 20480 + so,  Bhi + goB + q * 8);
            cp16(stg + 30720 + so,  Blo + goB + q * 8);
        }
    };

    load_stage(0); cp_commit();
    load_stage(1); cp_commit();

    for (int c = 0; c < nchunk; c++) {
        cp_wait1();
        __syncthreads();
        const bf16* sA_hi = (const bf16*)(smem_raw + (c & 1) * TG_STAGE);
        const bf16* sA_lo = sA_hi + 5120;
        const bf16* sB_hi = sA_hi + 10240;
        const bf16* sB_lo = sA_hi + 15360;

#pragma unroll
        for (int ks = 0; ks < 2; ks++) {
            unsigned ah[4][4], al[4][4];
#pragma unroll
            for (int mt = 0; mt < 4; mt++) {
                const int r = warpM * 64 + mt * 16 + (lane & 15);
                const int cc = ks * 16 + ((lane & 16) >> 1);
                ldsm_x4(ah[mt][0], ah[mt][1], ah[mt][2], ah[mt][3], saddr(sA_hi + r * 40 + cc));
                ldsm_x4(al[mt][0], al[mt][1], al[mt][2], al[mt][3], saddr(sA_lo + r * 40 + cc));
            }
#pragma unroll
            for (int ntp = 0; ntp < 4; ntp++) {
                const int r = warpN * 64 + ntp * 16 + (lane & 7) + ((lane & 16) >> 1);
                const int cc = ks * 16 + (lane & 8);
                unsigned bh[4], bl[4];
                ldsm_x4(bh[0], bh[1], bh[2], bh[3], saddr(sB_hi + r * 40 + cc));
                ldsm_x4(bl[0], bl[1], bl[2], bl[3], saddr(sB_lo + r * 40 + cc));
#pragma unroll
                for (int half = 0; half < 2; half++) {
                    const int nt = 2 * ntp + half;
#pragma unroll
                    for (int mt = 0; mt < 4; mt++) {
                        mma16816(acc[mt][nt], ah[mt][0], ah[mt][1], ah[mt][2], ah[mt][3],
                                 bh[2 * half], bh[2 * half + 1]);
                        mma16816(acc[mt][nt], ah[mt][0], ah[mt][1], ah[mt][2], ah[mt][3],
                                 bl[2 * half], bl[2 * half + 1]);
                        mma16816(acc[mt][nt], al[mt][0], al[mt][1], al[mt][2], al[mt][3],
                                 bh[2 * half], bh[2 * half + 1]);
                    }
                }
            }
        }
        __syncthreads();
        if (c + 2 < nchunk) load_stage(c + 2);
        cp_commit();
    }
}

// ---------------- fused QKV projection GEMM: N=3072, split-bf16 outputs ----------
__global__ __launch_bounds__(128) void tgemm_qkv(
    const bf16* __restrict__ Ahi, const bf16* __restrict__ Alo,
    const bf16* __restrict__ Bhi, const bf16* __restrict__ Blo,
    const float* __restrict__ b0, const float* __restrict__ b1, const float* __restrict__ b2,
    bf16* __restrict__ o0h, bf16* __restrict__ o0l,
    bf16* __restrict__ o1h, bf16* __restrict__ o1l,
    bf16* __restrict__ o2h, bf16* __restrict__ o2l)
{
    extern __shared__ __align__(16) char smem_raw[];
    const int brow = blockIdx.y * 128;
    const int bcol = blockIdx.x * 128;
    float acc[4][8][4];
    gemm_mainloop(Ahi, Alo, Bhi, Blo, brow, bcol, D_MODEL, smem_raw, acc);

    const int sel = bcol >> 10;
    const int ccol = bcol & 1023;
    const float* bias = (sel == 0) ? b0 : (sel == 1) ? b1 : b2;
    bf16* Chi = (sel == 0) ? o0h : (sel == 1) ? o1h : o2h;
    bf16* Clo = (sel == 0) ? o0l : (sel == 1) ? o1l : o2l;

    const int lane = threadIdx.x & 31;
    const int wid = threadIdx.x >> 5;
    const int warpM = wid & 1;
    const int warpN = wid >> 1;
#pragma unroll
    for (int mt = 0; mt < 4; mt++)
#pragma unroll
        for (int half = 0; half < 2; half++) {
            const int r = brow + warpM * 64 + mt * 16 + (lane >> 2) + half * 8;
#pragma unroll
            for (int nt = 0; nt < 8; nt++) {
                const int c = ccol + warpN * 64 + nt * 8 + 2 * (lane & 3);
                float2 bv = *(const float2*)(bias + c);
                float x = acc[mt][nt][half * 2 + 0] + bv.x;
                float y = acc[mt][nt][half * 2 + 1] + bv.y;
                unsigned h, l;
                split_pk(x, y, h, l);
                *(unsigned*)(Chi + (size_t)r * D_MODEL + c) = h;
                *(unsigned*)(Clo + (size_t)r * D_MODEL + c) = l;
            }
        }
}

// ---------------- fused O-projection GEMM (z selects branch), resid, fp32 out ----
__global__ __launch_bounds__(128) void tgemm_o(
    const bf16* __restrict__ A1h, const bf16* __restrict__ A1l,
    const bf16* __restrict__ A2h, const bf16* __restrict__ A2l,
    const bf16* __restrict__ Bhi, const bf16* __restrict__ Blo,
    const float* __restrict__ b1, const float* __restrict__ b2,
    const float* __restrict__ r1, const float* __restrict__ r2,
    float* __restrict__ t1, float* __restrict__ t2)
{
    extern __shared__ __align__(16) char smem_raw[];
    const int z = blockIdx.z;
    const int brow = blockIdx.y * 128;
    const int bcol = blockIdx.x * 128;
    const bf16* Ahi = z ? A2h : A1h;
    const bf16* Alo = z ? A2l : A1l;
    const float* bias = z ? b2 : b1;
    const float* resid = z ? r2 : r1;
    float* Cf = z ? t2 : t1;

    float acc[4][8][4];
    gemm_mainloop(Ahi, Alo, Bhi, Blo, brow, z * 1024 + bcol, D_MODEL, smem_raw, acc);

    const int lane = threadIdx.x & 31;
    const int wid = threadIdx.x >> 5;
    const int warpM = wid & 1;
    const int warpN = wid >> 1;
#pragma unroll
    for (int mt = 0; mt < 4; mt++)
#pragma unroll
        for (int half = 0; half < 2; half++) {
            const int r = brow + warpM * 64 + mt * 16 + (lane >> 2) + half * 8;
#pragma unroll
            for (int nt = 0; nt < 8; nt++) {
                const int c = bcol + warpN * 64 + nt * 8 + 2 * (lane & 3);
                float2 bv = *(const float2*)(bias + c);
                float2 rv = *(const float2*)(resid + (size_t)r * D_MODEL + c);
                float2 o2;
                o2.x = acc[mt][nt][half * 2 + 0] + bv.x + rv.x;
                o2.y = acc[mt][nt][half * 2 + 1] + bv.y + rv.y;
                *(float2*)(Cf + (size_t)r * D_MODEL + c) = o2;
            }
        }
}

// ---------------- standard GEMM: EPI 2 = bias+GELU->split; EPI 3 = bias->fp32 ----
template <int EPI>
__global__ __launch_bounds__(128) void tgemm(
    const bf16* __restrict__ Ahi, const bf16* __restrict__ Alo,
    const bf16* __restrict__ Bhi, const bf16* __restrict__ Blo,
    const float* __restrict__ bias,
    float* __restrict__ Cf, bf16* __restrict__ Chi, bf16* __restrict__ Clo, int K)
{
    extern __shared__ __align__(16) char smem_raw[];
    const int brow = blockIdx.y * 128;
    const int bcol = blockIdx.x * 128;
    float acc[4][8][4];
    gemm_mainloop(Ahi, Alo, Bhi, Blo, brow, bcol, K, smem_raw, acc);

    const int lane = threadIdx.x & 31;
    const int wid = threadIdx.x >> 5;
    const int warpM = wid & 1;
    const int warpN = wid >> 1;
#pragma unroll
    for (int mt = 0; mt < 4; mt++)
#pragma unroll
        for (int half = 0; half < 2; half++) {
            const int r = brow + warpM * 64 + mt * 16 + (lane >> 2) + half * 8;
#pragma unroll
            for (int nt = 0; nt < 8; nt++) {
                const int c = bcol + warpN * 64 + nt * 8 + 2 * (lane & 3);
                float2 bv = *(const float2*)(bias + c);
                float x = acc[mt][nt][half * 2 + 0] + bv.x;
                float y = acc[mt][nt][half * 2 + 1] + bv.y;
                if (EPI == 2) {
                    x = 0.5f * x * (1.0f + erff(x * 0.7071067811865475f));
                    y = 0.5f * y * (1.0f + erff(y * 0.7071067811865475f));
                    unsigned h, l;
                    split_pk(x, y, h, l);
                    *(unsigned*)(Chi + (size_t)r * D_MODEL + c) = h;
                    *(unsigned*)(Clo + (size_t)r * D_MODEL + c) = l;
                } else {
                    float2 o2; o2.x = x; o2.y = y;
                    *(float2*)(Cf + (size_t)r * D_MODEL + c) = o2;
                }
            }
        }
}

// ---------------- merged flash attention: 128 queries/CTA, 4 warps of 32 rows ----
#define AT_STAGE 36864
#define AT_QLO (2 * AT_STAGE)
#define AT_SMEM (2 * AT_STAGE + 18432)
__global__ __launch_bounds__(128) void attn_mma(
    const bf16* __restrict__ Q1h, const bf16* __restrict__ Q1l,
    const bf16* __restrict__ K1h, const bf16* __restrict__ K1l,
    const bf16* __restrict__ V1h, const bf16* __restrict__ V1l,
    bf16* __restrict__ O1h, bf16* __restrict__ O1l,
    const bf16* __restrict__ Q2h, const bf16* __restrict__ Q2l,
    const bf16* __restrict__ K2h, const bf16* __restrict__ K2l,
    const bf16* __restrict__ V2h, const bf16* __restrict__ V2l,
    bf16* __restrict__ O2h, bf16* __restrict__ O2l)
{
    extern __shared__ __align__(16) char smem_raw[];
    const int tid = threadIdx.x;
    const int lane = tid & 31;
    const int warp = tid >> 5;
    const int z = blockIdx.z;
    const int half2sel = z >> 2;
    const int b = z & 3;
    const int h = blockIdx.y;
    const int q0 = blockIdx.x * 128;
    const int hoff = h * HEAD_DIM;

    const bf16* Qh_ = half2sel ? Q2h : Q1h;
    const bf16* Ql_ = half2sel ? Q2l : Q1l;
    const bf16* Kh = half2sel ? K2h : K1h;
    const bf16* Kl = half2sel ? K2l : K1l;
    const bf16* Vh = half2sel ? V2h : V1h;
    const bf16* Vl = half2sel ? V2l : V1l;
    bf16* Ohi = half2sel ? O2h : O1h;
    bf16* Olo = half2sel ? O2l : O1l;

    const bf16* Qbh = Qh_ + (size_t)(b * SEQ + q0) * D_MODEL + hoff;
    const bf16* Qbl = Ql_ + (size_t)(b * SEQ + q0) * D_MODEL + hoff;
    const bf16* Kbh = Kh + (size_t)(b * SEQ) * D_MODEL + hoff;
    const bf16* Kbl = Kl + (size_t)(b * SEQ) * D_MODEL + hoff;
    const bf16* Vbh = Vh + (size_t)(b * SEQ) * D_MODEL + hoff;
    const bf16* Vbl = Vl + (size_t)(b * SEQ) * D_MODEL + hoff;

    // ---- stage Q: hi temp in stage0, lo persistent ----
    {
        bf16* qhi = (bf16*)smem_raw;
        bf16* qlo = (bf16*)(smem_raw + AT_QLO);
#pragma unroll
        for (int i = 0; i < 8; i++) {
            const int cid = i * 128 + tid;        // 0..1023
            const int row = cid >> 3;             // 0..127
            const int ch = cid & 7;
            *(uint4*)(qhi + row * 72 + 8 * ch) = *(const uint4*)(Qbh + (size_t)row * D_MODEL + 8 * ch);
            *(uint4*)(qlo + row * 72 + 8 * ch) = *(const uint4*)(Qbl + (size_t)row * D_MODEL + 8 * ch);
        }
    }
    __syncthreads();

    unsigned qh[2][4][4];
    {
        const bf16* qhi = (const bf16*)smem_raw;
#pragma unroll
        for (int mt = 0; mt < 2; mt++) {
            const int r = warp * 32 + mt * 16 + (lane & 15);
#pragma unroll
            for (int ks = 0; ks < 4; ks++) {
                const int c = ks * 16 + ((lane & 16) >> 1);
                ldsm_x4(qh[mt][ks][0], qh[mt][ks][1], qh[mt][ks][2], qh[mt][ks][3],
                        saddr(qhi + r * 72 + c));
            }
        }
    }
    __syncthreads();

    const unsigned sb = saddr(smem_raw);
    auto load_kv = [&](int t) {
        const unsigned stg = sb + (t & 1) * AT_STAGE;
        const int kt = t * 64;
#pragma unroll
        for (int i = 0; i < 4; i++) {
            const int cid = i * 128 + tid;
            const int row = cid >> 3;
            const int ch = cid & 7;
            const unsigned so = (unsigned)(row * 144 + ch * 16);
            const size_t go = (size_t)(kt + row) * D_MODEL + 8 * ch;
            cp16(stg + so,         Kbh + go);
            cp16(stg + 9216 + so,  Kbl + go);
            cp16(stg + 18432 + so, Vbh + go);
            cp16(stg + 27648 + so, Vbl + go);
        }
    };

    float o[2][8][4];
#pragma unroll
    for (int mt = 0; mt < 2; mt++)
#pragma unroll
        for (int jd = 0; jd < 8; jd++)
#pragma unroll
            for (int i = 0; i < 4; i++) o[mt][jd][i] = 0.0f;
    float run_m[2][2] = {{-1e30f, -1e30f}, {-1e30f, -1e30f}};
    float run_l[2][2] = {{0.0f, 0.0f}, {0.0f, 0.0f}};

    load_kv(0); cp_commit();
    load_kv(1); cp_commit();

    const int ntiles = SEQ / 64;
    for (int t = 0; t < ntiles; t++) {
        cp_wait1();
        __syncthreads();
        const bf16* skh = (const bf16*)(smem_raw + (t & 1) * AT_STAGE);
        const bf16* skl = skh + 4608;
        const bf16* svh = skh + 9216;
        const bf16* svl = skh + 13824;
        const bf16* qlo = (const bf16*)(smem_raw + AT_QLO);

        // ---- S = Q K^T ----
        float s[2][8][4];
#pragma unroll
        for (int mt = 0; mt < 2; mt++)
#pragma unroll
            for (int j = 0; j < 8; j++)
#pragma unroll
                for (int i = 0; i < 4; i++) s[mt][j][i] = 0.0f;
#pragma unroll
        for (int ks = 0; ks < 4; ks++) {
            unsigned qlf[2][4];
#pragma unroll
            for (int mt = 0; mt < 2; mt++) {
                const int r = warp * 32 + mt * 16 + (lane & 15);
                const int c = ks * 16 + ((lane & 16) >> 1);
                ldsm_x4(qlf[mt][0], qlf[mt][1], qlf[mt][2], qlf[mt][3],
                        saddr(qlo + r * 72 + c));
            }
#pragma unroll
            for (int ntp = 0; ntp < 4; ntp++) {
                const int r = ntp * 16 + (lane & 7) + ((lane & 16) >> 1);
                const int c = ks * 16 + (lane & 8);
                unsigned bh[4], bl[4];
                ldsm_x4(bh[0], bh[1], bh[2], bh[3], saddr(skh + r * 72 + c));
                ldsm_x4(bl[0], bl[1], bl[2], bl[3], saddr(skl + r * 72 + c));
#pragma unroll
                for (int hf = 0; hf < 2; hf++) {
                    const int j = 2 * ntp + hf;
#pragma unroll
                    for (int mt = 0; mt < 2; mt++) {
                        mma16816(s[mt][j], qh[mt][ks][0], qh[mt][ks][1], qh[mt][ks][2],
                                 qh[mt][ks][3], bh[2 * hf], bh[2 * hf + 1]);
                        mma16816(s[mt][j], qh[mt][ks][0], qh[mt][ks][1], qh[mt][ks][2],
                                 qh[mt][ks][3], bl[2 * hf], bl[2 * hf + 1]);
                        mma16816(s[mt][j], qlf[mt][0], qlf[mt][1], qlf[mt][2],
                                 qlf[mt][3], bh[2 * hf], bh[2 * hf + 1]);
                    }
                }
            }
        }
#pragma unroll
        for (int mt = 0; mt < 2; mt++)
#pragma unroll
            for (int j = 0; j < 8; j++)
#pragma unroll
                for (int i = 0; i < 4; i++) s[mt][j][i] *= 0.125f;

        // ---- online softmax per mt ----
#pragma unroll
        for (int mt = 0; mt < 2; mt++) {
            float tm1 = -1e30f, tm2 = -1e30f;
#pragma unroll
            for (int j = 0; j < 8; j++) {
                tm1 = fmaxf(tm1, fmaxf(s[mt][j][0], s[mt][j][1]));
                tm2 = fmaxf(tm2, fmaxf(s[mt][j][2], s[mt][j][3]));
            }
            tm1 = fmaxf(tm1, __shfl_xor_sync(0xffffffffu, tm1, 1));
            tm1 = fmaxf(tm1, __shfl_xor_sync(0xffffffffu, tm1, 2));
            tm2 = fmaxf(tm2, __shfl_xor_sync(0xffffffffu, tm2, 1));
            tm2 = fmaxf(tm2, __shfl_xor_sync(0xffffffffu, tm2, 2));
            const float nm1 = fmaxf(run_m[mt][0], tm1);
            const float nm2 = fmaxf(run_m[mt][1], tm2);
            const float sc1 = __expf(run_m[mt][0] - nm1);
            const float sc2 = __expf(run_m[mt][1] - nm2);
            run_m[mt][0] = nm1; run_m[mt][1] = nm2;

            float ts1 = 0.0f, ts2 = 0.0f;
#pragma unroll
            for (int j = 0; j < 8; j++) {
                s[mt][j][0] = __expf(s[mt][j][0] - nm1);
                s[mt][j][1] = __expf(s[mt][j][1] - nm1);
                s[mt][j][2] = __expf(s[mt][j][2] - nm2);
                s[mt][j][3] = __expf(s[mt][j][3] - nm2);
                ts1 += s[mt][j][0] + s[mt][j][1];
                ts2 += s[mt][j][2] + s[mt][j][3];
            }
            ts1 += __shfl_xor_sync(0xffffffffu, ts1, 1);
            ts1 += __shfl_xor_sync(0xffffffffu, ts1, 2);
            ts2 += __shfl_xor_sync(0xffffffffu, ts2, 1);
            ts2 += __shfl_xor_sync(0xffffffffu, ts2, 2);
            run_l[mt][0] = run_l[mt][0] * sc1 + ts1;
            run_l[mt][1] = run_l[mt][1] * sc2 + ts2;
#pragma unroll
            for (int jd = 0; jd < 8; jd++) {
                o[mt][jd][0] *= sc1; o[mt][jd][1] *= sc1;
                o[mt][jd][2] *= sc2; o[mt][jd][3] *= sc2;
            }
        }

        // ---- O += P V ----
#pragma unroll
        for (int kp = 0; kp < 4; kp++) {
            unsigned ph_[2][4], pl_[2][4];
#pragma unroll
            for (int mt = 0; mt < 2; mt++) {
                split_pk(s[mt][2 * kp][0],     s[mt][2 * kp][1],     ph_[mt][0], pl_[mt][0]);
                split_pk(s[mt][2 * kp][2],     s[mt][2 * kp][3],     ph_[mt][1], pl_[mt][1]);
                split_pk(s[mt][2 * kp + 1][0], s[mt][2 * kp + 1][1], ph_[mt][2], pl_[mt][2]);
                split_pk(s[mt][2 * kp + 1][2], s[mt][2 * kp + 1][3], ph_[mt][3], pl_[mt][3]);
            }
#pragma unroll
            for (int dntp = 0; dntp < 4; dntp++) {
                const int r = kp * 16 + (lane & 15);
                const int c = dntp * 16 + ((lane & 16) >> 1);
                unsigned vh[4], vl[4];
                ldsm_x4_t(vh[0], vh[1], vh[2], vh[3], saddr(svh + r * 72 + c));
                ldsm_x4_t(vl[0], vl[1], vl[2], vl[3], saddr(svl + r * 72 + c));
#pragma unroll
                for (int hf = 0; hf < 2; hf++) {
                    const int jd = 2 * dntp + hf;
#pragma unroll
                    for (int mt = 0; mt < 2; mt++) {
                        mma16816(o[mt][jd], ph_[mt][0], ph_[mt][1], ph_[mt][2], ph_[mt][3],
                                 vh[2 * hf], vh[2 * hf + 1]);
                        mma16816(o[mt][jd], ph_[mt][0], ph_[mt][1], ph_[mt][2], ph_[mt][3],
                                 vl[2 * hf], vl[2 * hf + 1]);
                        mma16816(o[mt][jd], pl_[mt][0], pl_[mt][1], pl_[mt][2], pl_[mt][3],
                                 vh[2 * hf], vh[2 * hf + 1]);
                    }
                }
            }
        }
        __syncthreads();
        if (t + 2 < ntiles) load_kv(t + 2);
        cp_commit();
    }

    // ---- write O as split bf16 ----
#pragma unroll
    for (int mt = 0; mt < 2; mt++) {
        const float i1 = 1.0f / run_l[mt][0];
        const float i2 = 1.0f / run_l[mt][1];
        const int r1 = b * SEQ + q0 + warp * 32 + mt * 16 + (lane >> 2);
#pragma unroll
        for (int jd = 0; jd < 8; jd++) {
            const int c = hoff + jd * 8 + 2 * (lane & 3);
            unsigned h0, l0, h1, l1;
            split_pk(o[mt][jd][0] * i1, o[mt][jd][1] * i1, h0, l0);
            split_pk(o[mt][jd][2] * i2, o[mt][jd][3] * i2, h1, l1);
            *(unsigned*)(Ohi + (size_t)r1 * D_MODEL + c) = h0;
            *(unsigned*)(Olo + (size_t)r1 * D_MODEL + c) = l0;
            *(unsigned*)(Ohi + (size_t)(r1 + 8) * D_MODEL + c) = h1;
            *(unsigned*)(Olo + (size_t)(r1 + 8) * D_MODEL + c) = l1;
        }
    }
}

// ---------------- LayerNorm core ----------------
__device__ __forceinline__ float4 ln_core(const float* x, const float* w,
                                          const float* b, int row, int tid) {
    float4 v = ((const float4*)(x + (size_t)row * D_MODEL))[tid];
    float s  = v.x + v.y + v.z + v.w;
    float s2 = v.x * v.x + v.y * v.y + v.z * v.z + v.w * v.w;
#pragma unroll
    for (int off = 16; off > 0; off >>= 1) {
        s  += __shfl_xor_sync(0xffffffffu, s, off);
        s2 += __shfl_xor_sync(0xffffffffu, s2, off);
    }
    __shared__ float rs[8], rs2[8];
    __shared__ float smu, sinv;
    const int wd = tid >> 5;
    if ((tid & 31) == 0) { rs[wd] = s; rs2[wd] = s2; }
    __syncthreads();
    if (tid == 0) {
        float ts = 0.0f, ts2 = 0.0f;
#pragma unroll
        for (int i = 0; i < 8; i++) { ts += rs[i]; ts2 += rs2[i]; }
        float mu  = ts * (1.0f / D_MODEL);
        float var = ts2 * (1.0f / D_MODEL) - mu * mu;
        smu = mu;
        sinv = rsqrtf(var + 1e-5f);
    }
    __syncthreads();
    const float mu = smu, inv = sinv;
    float4 wv = ((const float4*)w)[tid];
    float4 bv = ((const float4*)b)[tid];
    float4 ov;
    ov.x = (v.x - mu) * inv * wv.x + bv.x;
    ov.y = (v.y - mu) * inv * wv.y + bv.y;
    ov.z = (v.z - mu) * inv * wv.z + bv.z;
    ov.w = (v.w - mu) * inv * wv.w + bv.w;
    return ov;
}

__global__ __launch_bounds__(256) void ln2_kernel(
    const float* __restrict__ t1, const float* __restrict__ t2,
    const float* __restrict__ w1, const float* __restrict__ b1,
    const float* __restrict__ w2, const float* __restrict__ b2,
    bf16* __restrict__ cat_hi, bf16* __restrict__ cat_lo)
{
    const int row = blockIdx.x;
    const int sel = blockIdx.y;
    const int tid = threadIdx.x;
    float4 ov = ln_core(sel ? t2 : t1, sel ? w2 : w1, sel ? b2 : b1, row, tid);
    unsigned h0, l0, h1, l1;
    split_pk(ov.x, ov.y, h0, l0);
    split_pk(ov.z, ov.w, h1, l1);
    const size_t o = (size_t)row * 2048 + sel * 1024 + 4 * tid;
    unsigned* ph = (unsigned*)(cat_hi + o);
    unsigned* pl = (unsigned*)(cat_lo + o);
    ph[0] = h0; ph[1] = h1;
    pl[0] = l0; pl[1] = l1;
}

__global__ __launch_bounds__(256) void ln_final(
    const float* __restrict__ x, const float* __restrict__ w,
    const float* __restrict__ b, float* __restrict__ out)
{
    const int row = blockIdx.x;
    const int tid = threadIdx.x;
    float4 ov = ln_core(x, w, b, row, tid);
    ((float4*)(out + (size_t)row * D_MODEL))[tid] = ov;
}

// ---------------- orchestration ----------------
extern "C" void kernel_launch(void* const* d_in, const int* in_sizes, int n_in,
                              void* d_out, int out_size)
{
    (void)in_sizes; (void)n_in; (void)out_size;

    const float* temporal = (const float*)d_in[0];
    const float* feature  = (const float*)d_in[1];
    const float* qt_w = (const float*)d_in[2];  const float* qt_b = (const float*)d_in[3];
    const float* kf_w = (const float*)d_in[4];  const float* kf_b = (const float*)d_in[5];
    const float* vf_w = (const float*)d_in[6];  const float* vf_b = (const float*)d_in[7];
    const float* qf_w = (const float*)d_in[8];  const float* qf_b = (const float*)d_in[9];
    const float* kt_w = (const float*)d_in[10]; const float* kt_b = (const float*)d_in[11];
    const float* vt_w = (const float*)d_in[12]; const float* vt_b = (const float*)d_in[13];
    const float* ot_w = (const float*)d_in[14]; const float* ot_b = (const float*)d_in[15];
    const float* of_w = (const float*)d_in[16]; const float* of_b = (const float*)d_in[17];
    const float* fus1_w = (const float*)d_in[18]; const float* fus1_b = (const float*)d_in[19];
    const float* fus2_w = (const float*)d_in[20]; const float* fus2_b = (const float*)d_in[21];
    const float* ln_fus_w = (const float*)d_in[22]; const float* ln_fus_b = (const float*)d_in[23];
    const float* ln_t_w = (const float*)d_in[24]; const float* ln_t_b = (const float*)d_in[25];
    const float* ln_f_w = (const float*)d_in[26]; const float* ln_f_b = (const float*)d_in[27];
    float* out = (float*)d_out;

    bf16 *xt_hi, *xt_lo, *xf_hi, *xf_lo;
    bf16 *q1h, *q1l, *k1h, *k1l, *v1h, *v1l, *q2h, *q2l, *k2h, *k2l, *v2h, *v2l;
    bf16 *a1h, *a1l, *a2h, *a2l, *cat_hi, *cat_lo, *wp_hi, *wp_lo;
    float *t1, *t2;
    cudaGetSymbolAddress((void**)&xt_hi, g_xt_hi); cudaGetSymbolAddress((void**)&xt_lo, g_xt_lo);
    cudaGetSymbolAddress((void**)&xf_hi, g_xf_hi); cudaGetSymbolAddress((void**)&xf_lo, g_xf_lo);
    cudaGetSymbolAddress((void**)&q1h, g_q1h); cudaGetSymbolAddress((void**)&q1l, g_q1l);
    cudaGetSymbolAddress((void**)&k1h, g_k1h); cudaGetSymbolAddress((void**)&k1l, g_k1l);
    cudaGetSymbolAddress((void**)&v1h, g_v1h); cudaGetSymbolAddress((void**)&v1l, g_v1l);
    cudaGetSymbolAddress((void**)&q2h, g_q2h); cudaGetSymbolAddress((void**)&q2l, g_q2l);
    cudaGetSymbolAddress((void**)&k2h, g_k2h); cudaGetSymbolAddress((void**)&k2l, g_k2l);
    cudaGetSymbolAddress((void**)&v2h, g_v2h); cudaGetSymbolAddress((void**)&v2l, g_v2l);
    cudaGetSymbolAddress((void**)&a1h, g_a1h); cudaGetSymbolAddress((void**)&a1l, g_a1l);
    cudaGetSymbolAddress((void**)&a2h, g_a2h); cudaGetSymbolAddress((void**)&a2l, g_a2l);
    cudaGetSymbolAddress((void**)&cat_hi, g_cat_hi); cudaGetSymbolAddress((void**)&cat_lo, g_cat_lo);
    cudaGetSymbolAddress((void**)&wp_hi, g_wp_hi); cudaGetSymbolAddress((void**)&wp_lo, g_wp_lo);
    cudaGetSymbolAddress((void**)&t1, g_t1); cudaGetSymbolAddress((void**)&t2, g_t2);

    cudaFuncSetAttribute(tgemm_qkv, cudaFuncAttributeMaxDynamicSharedMemorySize, TG_SMEM);
    cudaFuncSetAttribute(tgemm_o,   cudaFuncAttributeMaxDynamicSharedMemorySize, TG_SMEM);
    cudaFuncSetAttribute(tgemm<2>,  cudaFuncAttributeMaxDynamicSharedMemorySize, TG_SMEM);
    cudaFuncSetAttribute(tgemm<3>,  cudaFuncAttributeMaxDynamicSharedMemorySize, TG_SMEM);
    cudaFuncSetAttribute(attn_mma,  cudaFuncAttributeMaxDynamicSharedMemorySize, AT_SMEM);

    const int nblk = (M_TOK * D_MODEL) / 1024;
    const dim3 tgrid(1024 / 32, 1024 / 32);
    const dim3 tgrid1(1024 / 32, 2048 / 32);
    const dim3 tblk(32, 8);
    const dim3 qkvgrid(3072 / 128, M_TOK / 128);      // (24, 64)
    const dim3 ggrid(D_MODEL / 128, M_TOK / 128);     // (8, 64)
    const dim3 ogrid(D_MODEL / 128, M_TOK / 128, 2);  // (8, 64, 2)
    const dim3 agrid(SEQ / 128, N_HEADS, 2 * BATCH);  // (16, 16, 8)
    const dim3 lngrid(M_TOK, 2);

    // ---- conversions ----
    split_kernel<<<nblk, 256>>>(temporal, xt_hi, xt_lo);
    split_kernel<<<nblk, 256>>>(feature,  xf_hi, xf_lo);
    wconv<<<tgrid, tblk>>>(qt_w, wp_hi + WOFF_QT, wp_lo + WOFF_QT, 1024, 1024);
    wconv<<<tgrid, tblk>>>(kt_w, wp_hi + WOFF_KT, wp_lo + WOFF_KT, 1024, 1024);
    wconv<<<tgrid, tblk>>>(vt_w, wp_hi + WOFF_VT, wp_lo + WOFF_VT, 1024, 1024);
    wconv<<<tgrid, tblk>>>(qf_w, wp_hi + WOFF_QF, wp_lo + WOFF_QF, 1024, 1024);
    wconv<<<tgrid, tblk>>>(kf_w, wp_hi + WOFF_KF, wp_lo + WOFF_KF, 1024, 1024);
    wconv<<<tgrid, tblk>>>(vf_w, wp_hi + WOFF_VF, wp_lo + WOFF_VF, 1024, 1024);
    wconv<<<tgrid, tblk>>>(ot_w, wp_hi + WOFF_OT, wp_lo + WOFF_OT, 1024, 1024);
    wconv<<<tgrid, tblk>>>(of_w, wp_hi + WOFF_OF, wp_lo + WOFF_OF, 1024, 1024);
    wconv<<<tgrid, tblk>>>(fus2_w, wp_hi + WOFF_F2, wp_lo + WOFF_F2, 1024, 1024);
    wconv<<<tgrid1, tblk>>>(fus1_w, wp_hi + WOFF_F1, wp_lo + WOFF_F1, 2048, 1024);

    // ---- fused QKV projections ----
    tgemm_qkv<<<qkvgrid, 128, TG_SMEM>>>(xt_hi, xt_lo, wp_hi + WOFF_QT, wp_lo + WOFF_QT,
                                         qt_b, kt_b, vt_b,
                                         q1h, q1l, k2h, k2l, v2h, v2l);
    tgemm_qkv<<<qkvgrid, 128, TG_SMEM>>>(xf_hi, xf_lo, wp_hi + WOFF_QF, wp_lo + WOFF_QF,
                                         qf_b, kf_b, vf_b,
                                         q2h, q2l, k1h, k1l, v1h, v1l);

    // ---- both attentions in one launch ----
    attn_mma<<<agrid, 128, AT_SMEM>>>(q1h, q1l, k1h, k1l, v1h, v1l, a1h, a1l,
                                      q2h, q2l, k2h, k2l, v2h, v2l, a2h, a2l);

    // ---- both O-projections in one launch ----
    tgemm_o<<<ogrid, 128, TG_SMEM>>>(a1h, a1l, a2h, a2l, wp_hi + WOFF_OT, wp_lo + WOFF_OT,
                                     ot_b, of_b, temporal, feature, t1, t2);

    // ---- both post-attn LayerNorms in one launch ----
    ln2_kernel<<<lngrid, 256>>>(t1, t2, ln_t_w, ln_t_b, ln_f_w, ln_f_b, cat_hi, cat_lo);

    // ---- fusion MLP ----
    tgemm<2><<<ggrid, 128, TG_SMEM>>>(cat_hi, cat_lo, wp_hi + WOFF_F1, wp_lo + WOFF_F1,
                                      fus1_b, nullptr, q1h, q1l, 2 * D_MODEL);
    tgemm<3><<<ggrid, 128, TG_SMEM>>>(q1h, q1l, wp_hi + WOFF_F2, wp_lo + WOFF_F2,
                                      fus2_b, t1, nullptr, nullptr, D_MODEL);
    ln_final<<<M_TOK, 256>>>(t1, ln_fus_w, ln_fus_b, out);
}

// round 16
// speedup vs baseline: 1.0430x; 1.0430x over previous
#include <cuda_runtime.h>
#include <cuda_bf16.h>
#include <math.h>
#include <stdint.h>

#define D_MODEL 1024
#define N_HEADS 16
#define HEAD_DIM 64
#define BATCH 4
#define SEQ 2048
#define M_TOK (BATCH * SEQ) /* 8192 */

typedef __nv_bfloat16 bf16;

#define NELEM ((size_t)M_TOK * D_MODEL)

// ---------------- scratch (allocation-free: __device__ globals) ----------------
__device__ bf16 g_xt_hi[NELEM], g_xt_lo[NELEM];
__device__ bf16 g_xf_hi[NELEM], g_xf_lo[NELEM];
__device__ bf16 g_q1h[NELEM], g_q1l[NELEM], g_k1h[NELEM], g_k1l[NELEM], g_v1h[NELEM], g_v1l[NELEM];
__device__ bf16 g_q2h[NELEM], g_q2l[NELEM], g_k2h[NELEM], g_k2l[NELEM], g_v2h[NELEM], g_v2l[NELEM];
__device__ bf16 g_a1h[NELEM], g_a1l[NELEM], g_a2h[NELEM], g_a2l[NELEM];
__device__ bf16 g_cat_hi[2 * NELEM], g_cat_lo[2 * NELEM];
__device__ float g_t1[NELEM], g_t2[NELEM];
__device__ bf16 g_wp_hi[11u * 1024u * 1024u];
__device__ bf16 g_wp_lo[11u * 1024u * 1024u];

#define WOFF_QT 0u
#define WOFF_KT (1u * 1048576u)
#define WOFF_VT (2u * 1048576u)
#define WOFF_QF (3u * 1048576u)
#define WOFF_KF (4u * 1048576u)
#define WOFF_VF (5u * 1048576u)
#define WOFF_OT (6u * 1048576u)
#define WOFF_OF (7u * 1048576u)
#define WOFF_F2 (8u * 1048576u)
#define WOFF_F1 (9u * 1048576u)

// ---------------- helpers ----------------
__device__ __forceinline__ void split_pk(float a, float b, unsigned &hi, unsigned &lo) {
    bf16 ah = __float2bfloat16_rn(a);
    bf16 bh = __float2bfloat16_rn(b);
    hi = ((unsigned)__bfloat16_as_ushort(bh) << 16) | (unsigned)__bfloat16_as_ushort(ah);
    float ar = a - __bfloat162float(ah);
    float br = b - __bfloat162float(bh);
    lo = ((unsigned)__bfloat16_as_ushort(__float2bfloat16_rn(br)) << 16) |
         (unsigned)__bfloat16_as_ushort(__float2bfloat16_rn(ar));
}

__device__ __forceinline__ void mma16816(float* d, unsigned a0, unsigned a1,
                                         unsigned a2, unsigned a3,
                                         unsigned b0, unsigned b1) {
    asm volatile(
        "mma.sync.aligned.m16n8k16.row.col.f32.bf16.bf16.f32 "
        "{%0,%1,%2,%3},{%4,%5,%6,%7},{%8,%9},{%0,%1,%2,%3};"
        : "+f"(d[0]), "+f"(d[1]), "+f"(d[2]), "+f"(d[3])
        : "r"(a0), "r"(a1), "r"(a2), "r"(a3), "r"(b0), "r"(b1));
}

__device__ __forceinline__ unsigned saddr(const void* p) {
    return (unsigned)__cvta_generic_to_shared(p);
}
__device__ __forceinline__ void ldsm_x4(unsigned &r0, unsigned &r1, unsigned &r2,
                                        unsigned &r3, unsigned a) {
    asm volatile("ldmatrix.sync.aligned.m8n8.x4.shared.b16 {%0,%1,%2,%3},[%4];"
                 : "=r"(r0), "=r"(r1), "=r"(r2), "=r"(r3) : "r"(a));
}
__device__ __forceinline__ void ldsm_x4_t(unsigned &r0, unsigned &r1, unsigned &r2,
                                          unsigned &r3, unsigned a) {
    asm volatile("ldmatrix.sync.aligned.m8n8.x4.trans.shared.b16 {%0,%1,%2,%3},[%4];"
                 : "=r"(r0), "=r"(r1), "=r"(r2), "=r"(r3) : "r"(a));
}
__device__ __forceinline__ void cp16(unsigned dst, const void* src) {
    asm volatile("cp.async.cg.shared.global [%0], [%1], 16;" :: "r"(dst), "l"(src));
}
__device__ __forceinline__ void cp_commit() {
    asm volatile("cp.async.commit_group;");
}
__device__ __forceinline__ void cp_wait1() {
    asm volatile("cp.async.wait_group 1;" ::: "memory");
}

// ---------------- converters ----------------
__global__ __launch_bounds__(256) void split_kernel(
    const float* __restrict__ in, bf16* __restrict__ hi, bf16* __restrict__ lo)
{
    const size_t i = (size_t)blockIdx.x * 256 + threadIdx.x;
    float4 v = ((const float4*)in)[i];
    unsigned h0, l0, h1, l1;
    split_pk(v.x, v.y, h0, l0);
    split_pk(v.z, v.w, h1, l1);
    uint2 hh; hh.x = h0; hh.y = h1;
    uint2 ll; ll.x = l0; ll.y = l1;
    ((uint2*)hi)[i] = hh;
    ((uint2*)lo)[i] = ll;
}

// W[K][N] fp32 -> T[N][K] split bf16
__global__ __launch_bounds__(256) void wconv(
    const float* __restrict__ W, bf16* __restrict__ Thi, bf16* __restrict__ Tlo,
    int K, int N)
{
    __shared__ float tile[32][33];
    const int tx = threadIdx.x, ty = threadIdx.y;
    const int n0 = blockIdx.x * 32;
    const int k0 = blockIdx.y * 32;
#pragma unroll
    for (int i = 0; i < 4; i++)
        tile[ty + 8 * i][tx] = W[(size_t)(k0 + ty + 8 * i) * N + n0 + tx];
    __syncthreads();
#pragma unroll
    for (int i = 0; i < 4; i++) {
        float v = tile[tx][ty + 8 * i];
        bf16 h = __float2bfloat16_rn(v);
        const size_t o = (size_t)(n0 + ty + 8 * i) * K + k0 + tx;
        Thi[o] = h;
        Tlo[o] = __float2bfloat16_rn(v - __bfloat162float(h));
    }
}

// ---------------- shared GEMM mainloop (round-11 shape: 256 thr, 8 warps 32x64) ----
#define TG_STAGE 40960
#define TG_SMEM (2 * TG_STAGE)
__device__ __forceinline__ void gemm_mainloop(
    const bf16* __restrict__ Ahi, const bf16* __restrict__ Alo,
    const bf16* __restrict__ Bhi, const bf16* __restrict__ Blo,
    int brow, int browB, int K, char* smem_raw, float acc[2][8][4])
{
    const int tid = threadIdx.x;
    const int lane = tid & 31;
    const int wid = tid >> 5;
    const int warpM = wid & 3;
    const int warpN = wid >> 2;
    const unsigned sb = saddr(smem_raw);
    const int nchunk = K >> 5;

#pragma unroll
    for (int mt = 0; mt < 2; mt++)
#pragma unroll
        for (int nt = 0; nt < 8; nt++)
#pragma unroll
            for (int i = 0; i < 4; i++) acc[mt][nt][i] = 0.0f;

    auto load_stage = [&](int c) {
        const unsigned stg = sb + (c & 1) * TG_STAGE;
        const int k0 = c * 32;
#pragma unroll
        for (int q = 0; q < 2; q++) {
            const int cid = tid * 2 + q;
            const int r = cid >> 2;
            const int cb = cid & 3;
            const unsigned so = (unsigned)(r * 80 + cb * 16);
            const size_t goA = (size_t)(brow + r) * K + k0 + cb * 8;
            const size_t goB = (size_t)(browB + r) * K + k0 + cb * 8;
            cp16(stg + so,          Ahi + goA);
            cp16(stg + 10240 + so,  Alo + goA);
            cp16(stg + 20480 + so,  Bhi + goB);
            cp16(stg + 30720 + so,  Blo + goB);
        }
    };

    load_stage(0); cp_commit();
    load_stage(1); cp_commit();

    for (int c = 0; c < nchunk; c++) {
        cp_wait1();
        __syncthreads();
        const bf16* sA_hi = (const bf16*)(smem_raw + (c & 1) * TG_STAGE);
        const bf16* sA_lo = sA_hi + 5120;
        const bf16* sB_hi = sA_hi + 10240;
        const bf16* sB_lo = sA_hi + 15360;

#pragma unroll
        for (int ks = 0; ks < 2; ks++) {
            unsigned ah[2][4], al[2][4];
#pragma unroll
            for (int mt = 0; mt < 2; mt++) {
                const int r = warpM * 32 + mt * 16 + (lane & 15);
                const int cc = ks * 16 + ((lane & 16) >> 1);
                ldsm_x4(ah[mt][0], ah[mt][1], ah[mt][2], ah[mt][3], saddr(sA_hi + r * 40 + cc));
                ldsm_x4(al[mt][0], al[mt][1], al[mt][2], al[mt][3], saddr(sA_lo + r * 40 + cc));
            }
#pragma unroll
            for (int ntp = 0; ntp < 4; ntp++) {
                const int r = warpN * 64 + ntp * 16 + (lane & 7) + ((lane & 16) >> 1);
                const int cc = ks * 16 + (lane & 8);
                unsigned bh[4], bl[4];
                ldsm_x4(bh[0], bh[1], bh[2], bh[3], saddr(sB_hi + r * 40 + cc));
                ldsm_x4(bl[0], bl[1], bl[2], bl[3], saddr(sB_lo + r * 40 + cc));
#pragma unroll
                for (int half = 0; half < 2; half++) {
                    const int nt = 2 * ntp + half;
#pragma unroll
                    for (int mt = 0; mt < 2; mt++) {
                        mma16816(acc[mt][nt], ah[mt][0], ah[mt][1], ah[mt][2], ah[mt][3],
                                 bh[2 * half], bh[2 * half + 1]);
                        mma16816(acc[mt][nt], ah[mt][0], ah[mt][1], ah[mt][2], ah[mt][3],
                                 bl[2 * half], bl[2 * half + 1]);
                        mma16816(acc[mt][nt], al[mt][0], al[mt][1], al[mt][2], al[mt][3],
                                 bh[2 * half], bh[2 * half + 1]);
                    }
                }
            }
        }
        __syncthreads();
        if (c + 2 < nchunk) load_stage(c + 2);
        cp_commit();
    }
}

// ---------------- fused QKV projection GEMM: N=3072, split-bf16 outputs ----------
__global__ __launch_bounds__(256, 2) void tgemm_qkv(
    const bf16* __restrict__ Ahi, const bf16* __restrict__ Alo,
    const bf16* __restrict__ Bhi, const bf16* __restrict__ Blo,
    const float* __restrict__ b0, const float* __restrict__ b1, const float* __restrict__ b2,
    bf16* __restrict__ o0h, bf16* __restrict__ o0l,
    bf16* __restrict__ o1h, bf16* __restrict__ o1l,
    bf16* __restrict__ o2h, bf16* __restrict__ o2l)
{
    extern __shared__ __align__(16) char smem_raw[];
    const int brow = blockIdx.y * 128;
    const int bcol = blockIdx.x * 128;
    float acc[2][8][4];
    gemm_mainloop(Ahi, Alo, Bhi, Blo, brow, bcol, D_MODEL, smem_raw, acc);

    const int sel = bcol >> 10;
    const int ccol = bcol & 1023;
    const float* bias = (sel == 0) ? b0 : (sel == 1) ? b1 : b2;
    bf16* Chi = (sel == 0) ? o0h : (sel == 1) ? o1h : o2h;
    bf16* Clo = (sel == 0) ? o0l : (sel == 1) ? o1l : o2l;

    const int lane = threadIdx.x & 31;
    const int wid = threadIdx.x >> 5;
    const int warpM = wid & 3;
    const int warpN = wid >> 2;
#pragma unroll
    for (int mt = 0; mt < 2; mt++)
#pragma unroll
        for (int half = 0; half < 2; half++) {
            const int r = brow + warpM * 32 + mt * 16 + (lane >> 2) + half * 8;
#pragma unroll
            for (int nt = 0; nt < 8; nt++) {
                const int c = ccol + warpN * 64 + nt * 8 + 2 * (lane & 3);
                float2 bv = *(const float2*)(bias + c);
                float x = acc[mt][nt][half * 2 + 0] + bv.x;
                float y = acc[mt][nt][half * 2 + 1] + bv.y;
                unsigned h, l;
                split_pk(x, y, h, l);
                *(unsigned*)(Chi + (size_t)r * D_MODEL + c) = h;
                *(unsigned*)(Clo + (size_t)r * D_MODEL + c) = l;
            }
        }
}

// ---------------- fused O-projection GEMM (z selects branch), resid, fp32 out ----
__global__ __launch_bounds__(256, 2) void tgemm_o(
    const bf16* __restrict__ A1h, const bf16* __restrict__ A1l,
    const bf16* __restrict__ A2h, const bf16* __restrict__ A2l,
    const bf16* __restrict__ Bhi, const bf16* __restrict__ Blo,
    const float* __restrict__ b1, const float* __restrict__ b2,
    const float* __restrict__ r1, const float* __restrict__ r2,
    float* __restrict__ t1, float* __restrict__ t2)
{
    extern __shared__ __align__(16) char smem_raw[];
    const int z = blockIdx.z;
    const int brow = blockIdx.y * 128;
    const int bcol = blockIdx.x * 128;
    const bf16* Ahi = z ? A2h : A1h;
    const bf16* Alo = z ? A2l : A1l;
    const float* bias = z ? b2 : b1;
    const float* resid = z ? r2 : r1;
    float* Cf = z ? t2 : t1;

    float acc[2][8][4];
    gemm_mainloop(Ahi, Alo, Bhi, Blo, brow, z * 1024 + bcol, D_MODEL, smem_raw, acc);

    const int lane = threadIdx.x & 31;
    const int wid = threadIdx.x >> 5;
    const int warpM = wid & 3;
    const int warpN = wid >> 2;
#pragma unroll
    for (int mt = 0; mt < 2; mt++)
#pragma unroll
        for (int half = 0; half < 2; half++) {
            const int r = brow + warpM * 32 + mt * 16 + (lane >> 2) + half * 8;
#pragma unroll
            for (int nt = 0; nt < 8; nt++) {
                const int c = bcol + warpN * 64 + nt * 8 + 2 * (lane & 3);
                float2 bv = *(const float2*)(bias + c);
                float2 rv = *(const float2*)(resid + (size_t)r * D_MODEL + c);
                float2 o2;
                o2.x = acc[mt][nt][half * 2 + 0] + bv.x + rv.x;
                o2.y = acc[mt][nt][half * 2 + 1] + bv.y + rv.y;
                *(float2*)(Cf + (size_t)r * D_MODEL + c) = o2;
            }
        }
}

// ---------------- standard GEMM: EPI 2 = bias+GELU->split; EPI 3 = bias->fp32 ----
template <int EPI>
__global__ __launch_bounds__(256, 2) void tgemm(
    const bf16* __restrict__ Ahi, const bf16* __restrict__ Alo,
    const bf16* __restrict__ Bhi, const bf16* __restrict__ Blo,
    const float* __restrict__ bias,
    float* __restrict__ Cf, bf16* __restrict__ Chi, bf16* __restrict__ Clo, int K)
{
    extern __shared__ __align__(16) char smem_raw[];
    const int brow = blockIdx.y * 128;
    const int bcol = blockIdx.x * 128;
    float acc[2][8][4];
    gemm_mainloop(Ahi, Alo, Bhi, Blo, brow, bcol, K, smem_raw, acc);

    const int lane = threadIdx.x & 31;
    const int wid = threadIdx.x >> 5;
    const int warpM = wid & 3;
    const int warpN = wid >> 2;
#pragma unroll
    for (int mt = 0; mt < 2; mt++)
#pragma unroll
        for (int half = 0; half < 2; half++) {
            const int r = brow + warpM * 32 + mt * 16 + (lane >> 2) + half * 8;
#pragma unroll
            for (int nt = 0; nt < 8; nt++) {
                const int c = bcol + warpN * 64 + nt * 8 + 2 * (lane & 3);
                float2 bv = *(const float2*)(bias + c);
                float x = acc[mt][nt][half * 2 + 0] + bv.x;
                float y = acc[mt][nt][half * 2 + 1] + bv.y;
                if (EPI == 2) {
                    x = 0.5f * x * (1.0f + erff(x * 0.7071067811865475f));
                    y = 0.5f * y * (1.0f + erff(y * 0.7071067811865475f));
                    unsigned h, l;
                    split_pk(x, y, h, l);
                    *(unsigned*)(Chi + (size_t)r * D_MODEL + c) = h;
                    *(unsigned*)(Clo + (size_t)r * D_MODEL + c) = l;
                } else {
                    float2 o2; o2.x = x; o2.y = y;
                    *(float2*)(Cf + (size_t)r * D_MODEL + c) = o2;
                }
            }
        }
}

// ---------------- merged flash attention: 128 q/CTA, 256 thr, 8 warps x 16 rows ----
#define AT_STAGE 36864
#define AT_SMEM (2 * AT_STAGE)
__global__ __launch_bounds__(256) void attn_mma(
    const bf16* __restrict__ Q1h, const bf16* __restrict__ Q1l,
    const bf16* __restrict__ K1h, const bf16* __restrict__ K1l,
    const bf16* __restrict__ V1h, const bf16* __restrict__ V1l,
    bf16* __restrict__ O1h, bf16* __restrict__ O1l,
    const bf16* __restrict__ Q2h, const bf16* __restrict__ Q2l,
    const bf16* __restrict__ K2h, const bf16* __restrict__ K2l,
    const bf16* __restrict__ V2h, const bf16* __restrict__ V2l,
    bf16* __restrict__ O2h, bf16* __restrict__ O2l)
{
    extern __shared__ __align__(16) char smem_raw[];
    const int tid = threadIdx.x;
    const int lane = tid & 31;
    const int warp = tid >> 5;                 // 0..7, warp owns q rows [16w,16w+16)
    const int z = blockIdx.z;
    const int half2sel = z >> 2;
    const int b = z & 3;
    const int h = blockIdx.y;
    const int q0 = blockIdx.x * 128;
    const int hoff = h * HEAD_DIM;

    const bf16* Qh_ = half2sel ? Q2h : Q1h;
    const bf16* Ql_ = half2sel ? Q2l : Q1l;
    const bf16* Kh = half2sel ? K2h : K1h;
    const bf16* Kl = half2sel ? K2l : K1l;
    const bf16* Vh = half2sel ? V2h : V1h;
    const bf16* Vl = half2sel ? V2l : V1l;
    bf16* Ohi = half2sel ? O2h : O1h;
    bf16* Olo = half2sel ? O2l : O1l;

    const bf16* Qbh = Qh_ + (size_t)(b * SEQ + q0) * D_MODEL + hoff;
    const bf16* Qbl = Ql_ + (size_t)(b * SEQ + q0) * D_MODEL + hoff;
    const bf16* Kbh = Kh + (size_t)(b * SEQ) * D_MODEL + hoff;
    const bf16* Kbl = Kl + (size_t)(b * SEQ) * D_MODEL + hoff;
    const bf16* Vbh = Vh + (size_t)(b * SEQ) * D_MODEL + hoff;
    const bf16* Vbl = Vl + (size_t)(b * SEQ) * D_MODEL + hoff;

    // ---- stage Q (128 rows, hi + lo fills stage0 exactly), extract fragments ----
    {
        bf16* qhi = (bf16*)smem_raw;
        bf16* qlo = qhi + 9216;               // 128*72 elements
#pragma unroll
        for (int i = 0; i < 4; i++) {
            const int cid = i * 256 + tid;     // 0..1023
            const int row = cid >> 3;          // 0..127
            const int ch = cid & 7;
            *(uint4*)(qhi + row * 72 + 8 * ch) = *(const uint4*)(Qbh + (size_t)row * D_MODEL + 8 * ch);
            *(uint4*)(qlo + row * 72 + 8 * ch) = *(const uint4*)(Qbl + (size_t)row * D_MODEL + 8 * ch);
        }
    }
    __syncthreads();

    unsigned qh[4][4], ql[4][4];
    {
        const bf16* qhi = (const bf16*)smem_raw;
        const bf16* qlo = qhi + 9216;
        const int r = warp * 16 + (lane & 15);
#pragma unroll
        for (int ks = 0; ks < 4; ks++) {
            const int c = ks * 16 + ((lane & 16) >> 1);
            ldsm_x4(qh[ks][0], qh[ks][1], qh[ks][2], qh[ks][3], saddr(qhi + r * 72 + c));
            ldsm_x4(ql[ks][0], ql[ks][1], ql[ks][2], ql[ks][3], saddr(qlo + r * 72 + c));
        }
    }
    __syncthreads();

    const unsigned sb = saddr(smem_raw);
    auto load_kv = [&](int t) {
        const unsigned stg = sb + (t & 1) * AT_STAGE;
        const int kt = t * 64;
#pragma unroll
        for (int i = 0; i < 2; i++) {
            const int cid = i * 256 + tid;     // 0..511
            const int row = cid >> 3;          // 0..63
            const int ch = cid & 7;
            const unsigned so = (unsigned)(row * 144 + ch * 16);
            const size_t go = (size_t)(kt + row) * D_MODEL + 8 * ch;
            cp16(stg + so,         Kbh + go);
            cp16(stg + 9216 + so,  Kbl + go);
            cp16(stg + 18432 + so, Vbh + go);
            cp16(stg + 27648 + so, Vbl + go);
        }
    };

    float o[8][4];
#pragma unroll
    for (int jd = 0; jd < 8; jd++)
#pragma unroll
        for (int i = 0; i < 4; i++) o[jd][i] = 0.0f;
    float run_m1 = -1e30f, run_m2 = -1e30f, run_l1 = 0.0f, run_l2 = 0.0f;

    load_kv(0); cp_commit();
    load_kv(1); cp_commit();

    const int ntiles = SEQ / 64;
    for (int t = 0; t < ntiles; t++) {
        cp_wait1();
        __syncthreads();
        const bf16* skh = (const bf16*)(smem_raw + (t & 1) * AT_STAGE);
        const bf16* skl = skh + 4608;
        const bf16* svh = skh + 9216;
        const bf16* svl = skh + 13824;

        // ---- S = Q K^T ----
        float s[8][4];
#pragma unroll
        for (int j = 0; j < 8; j++)
#pragma unroll
            for (int i = 0; i < 4; i++) s[j][i] = 0.0f;
#pragma unroll
        for (int ks = 0; ks < 4; ks++) {
#pragma unroll
            for (int ntp = 0; ntp < 4; ntp++) {
                const int r = ntp * 16 + (lane & 7) + ((lane & 16) >> 1);
                const int c = ks * 16 + (lane & 8);
                unsigned bh[4], bl[4];
                ldsm_x4(bh[0], bh[1], bh[2], bh[3], saddr(skh + r * 72 + c));
                ldsm_x4(bl[0], bl[1], bl[2], bl[3], saddr(skl + r * 72 + c));
#pragma unroll
                for (int hf = 0; hf < 2; hf++) {
                    const int j = 2 * ntp + hf;
                    mma16816(s[j], qh[ks][0], qh[ks][1], qh[ks][2], qh[ks][3],
                             bh[2 * hf], bh[2 * hf + 1]);
                    mma16816(s[j], qh[ks][0], qh[ks][1], qh[ks][2], qh[ks][3],
                             bl[2 * hf], bl[2 * hf + 1]);
                    mma16816(s[j], ql[ks][0], ql[ks][1], ql[ks][2], ql[ks][3],
                             bh[2 * hf], bh[2 * hf + 1]);
                }
            }
        }
#pragma unroll
        for (int j = 0; j < 8; j++)
#pragma unroll
            for (int i = 0; i < 4; i++) s[j][i] *= 0.125f;

        // ---- online softmax ----
        float tm1 = -1e30f, tm2 = -1e30f;
#pragma unroll
        for (int j = 0; j < 8; j++) {
            tm1 = fmaxf(tm1, fmaxf(s[j][0], s[j][1]));
            tm2 = fmaxf(tm2, fmaxf(s[j][2], s[j][3]));
        }
        tm1 = fmaxf(tm1, __shfl_xor_sync(0xffffffffu, tm1, 1));
        tm1 = fmaxf(tm1, __shfl_xor_sync(0xffffffffu, tm1, 2));
        tm2 = fmaxf(tm2, __shfl_xor_sync(0xffffffffu, tm2, 1));
        tm2 = fmaxf(tm2, __shfl_xor_sync(0xffffffffu, tm2, 2));
        const float nm1 = fmaxf(run_m1, tm1);
        const float nm2 = fmaxf(run_m2, tm2);
        const float sc1 = __expf(run_m1 - nm1);
        const float sc2 = __expf(run_m2 - nm2);
        run_m1 = nm1; run_m2 = nm2;

        float ts1 = 0.0f, ts2 = 0.0f;
#pragma unroll
        for (int j = 0; j < 8; j++) {
            s[j][0] = __expf(s[j][0] - nm1);
            s[j][1] = __expf(s[j][1] - nm1);
            s[j][2] = __expf(s[j][2] - nm2);
            s[j][3] = __expf(s[j][3] - nm2);
            ts1 += s[j][0] + s[j][1];
            ts2 += s[j][2] + s[j][3];
        }
        ts1 += __shfl_xor_sync(0xffffffffu, ts1, 1);
        ts1 += __shfl_xor_sync(0xffffffffu, ts1, 2);
        ts2 += __shfl_xor_sync(0xffffffffu, ts2, 1);
        ts2 += __shfl_xor_sync(0xffffffffu, ts2, 2);
        run_l1 = run_l1 * sc1 + ts1;
        run_l2 = run_l2 * sc2 + ts2;
#pragma unroll
        for (int jd = 0; jd < 8; jd++) {
            o[jd][0] *= sc1; o[jd][1] *= sc1;
            o[jd][2] *= sc2; o[jd][3] *= sc2;
        }

        // ---- O += P V ----
#pragma unroll
        for (int kp = 0; kp < 4; kp++) {
            unsigned ph_[4], pl_[4];
            split_pk(s[2 * kp][0],     s[2 * kp][1],     ph_[0], pl_[0]);
            split_pk(s[2 * kp][2],     s[2 * kp][3],     ph_[1], pl_[1]);
            split_pk(s[2 * kp + 1][0], s[2 * kp + 1][1], ph_[2], pl_[2]);
            split_pk(s[2 * kp + 1][2], s[2 * kp + 1][3], ph_[3], pl_[3]);
#pragma unroll
            for (int dntp = 0; dntp < 4; dntp++) {
                const int r = kp * 16 + (lane & 15);
                const int c = dntp * 16 + ((lane & 16) >> 1);
                unsigned vh[4], vl[4];
                ldsm_x4_t(vh[0], vh[1], vh[2], vh[3], saddr(svh + r * 72 + c));
                ldsm_x4_t(vl[0], vl[1], vl[2], vl[3], saddr(svl + r * 72 + c));
#pragma unroll
                for (int hf = 0; hf < 2; hf++) {
                    const int jd = 2 * dntp + hf;
                    mma16816(o[jd], ph_[0], ph_[1], ph_[2], ph_[3], vh[2 * hf], vh[2 * hf + 1]);
                    mma16816(o[jd], ph_[0], ph_[1], ph_[2], ph_[3], vl[2 * hf], vl[2 * hf + 1]);
                    mma16816(o[jd], pl_[0], pl_[1], pl_[2], pl_[3], vh[2 * hf], vh[2 * hf + 1]);
                }
            }
        }
        __syncthreads();
        if (t + 2 < ntiles) load_kv(t + 2);
        cp_commit();
    }

    // ---- write O as split bf16 ----
    const float i1 = 1.0f / run_l1;
    const float i2 = 1.0f / run_l2;
    const int r1 = b * SEQ + q0 + warp * 16 + (lane >> 2);
#pragma unroll
    for (int jd = 0; jd < 8; jd++) {
        const int c = hoff + jd * 8 + 2 * (lane & 3);
        unsigned h0, l0, h1, l1;
        split_pk(o[jd][0] * i1, o[jd][1] * i1, h0, l0);
        split_pk(o[jd][2] * i2, o[jd][3] * i2, h1, l1);
        *(unsigned*)(Ohi + (size_t)r1 * D_MODEL + c) = h0;
        *(unsigned*)(Olo + (size_t)r1 * D_MODEL + c) = l0;
        *(unsigned*)(Ohi + (size_t)(r1 + 8) * D_MODEL + c) = h1;
        *(unsigned*)(Olo + (size_t)(r1 + 8) * D_MODEL + c) = l1;
    }
}

// ---------------- LayerNorm core ----------------
__device__ __forceinline__ float4 ln_core(const float* x, const float* w,
                                          const float* b, int row, int tid) {
    float4 v = ((const float4*)(x + (size_t)row * D_MODEL))[tid];
    float s  = v.x + v.y + v.z + v.w;
    float s2 = v.x * v.x + v.y * v.y + v.z * v.z + v.w * v.w;
#pragma unroll
    for (int off = 16; off > 0; off >>= 1) {
        s  += __shfl_xor_sync(0xffffffffu, s, off);
        s2 += __shfl_xor_sync(0xffffffffu, s2, off);
    }
    __shared__ float rs[8], rs2[8];
    __shared__ float smu, sinv;
    const int wd = tid >> 5;
    if ((tid & 31) == 0) { rs[wd] = s; rs2[wd] = s2; }
    __syncthreads();
    if (tid == 0) {
        float ts = 0.0f, ts2 = 0.0f;
#pragma unroll
        for (int i = 0; i < 8; i++) { ts += rs[i]; ts2 += rs2[i]; }
        float mu  = ts * (1.0f / D_MODEL);
        float var = ts2 * (1.0f / D_MODEL) - mu * mu;
        smu = mu;
        sinv = rsqrtf(var + 1e-5f);
    }
    __syncthreads();
    const float mu = smu, inv = sinv;
    float4 wv = ((const float4*)w)[tid];
    float4 bv = ((const float4*)b)[tid];
    float4 ov;
    ov.x = (v.x - mu) * inv * wv.x + bv.x;
    ov.y = (v.y - mu) * inv * wv.y + bv.y;
    ov.z = (v.z - mu) * inv * wv.z + bv.z;
    ov.w = (v.w - mu) * inv * wv.w + bv.w;
    return ov;
}

__global__ __launch_bounds__(256) void ln2_kernel(
    const float* __restrict__ t1, const float* __restrict__ t2,
    const float* __restrict__ w1, const float* __restrict__ b1,
    const float* __restrict__ w2, const float* __restrict__ b2,
    bf16* __restrict__ cat_hi, bf16* __restrict__ cat_lo)
{
    const int row = blockIdx.x;
    const int sel = blockIdx.y;
    const int tid = threadIdx.x;
    float4 ov = ln_core(sel ? t2 : t1, sel ? w2 : w1, sel ? b2 : b1, row, tid);
    unsigned h0, l0, h1, l1;
    split_pk(ov.x, ov.y, h0, l0);
    split_pk(ov.z, ov.w, h1, l1);
    const size_t o = (size_t)row * 2048 + sel * 1024 + 4 * tid;
    unsigned* ph = (unsigned*)(cat_hi + o);
    unsigned* pl = (unsigned*)(cat_lo + o);
    ph[0] = h0; ph[1] = h1;
    pl[0] = l0; pl[1] = l1;
}

__global__ __launch_bounds__(256) void ln_final(
    const float* __restrict__ x, const float* __restrict__ w,
    const float* __restrict__ b, float* __restrict__ out)
{
    const int row = blockIdx.x;
    const int tid = threadIdx.x;
    float4 ov = ln_core(x, w, b, row, tid);
    ((float4*)(out + (size_t)row * D_MODEL))[tid] = ov;
}

// ---------------- orchestration ----------------
extern "C" void kernel_launch(void* const* d_in, const int* in_sizes, int n_in,
                              void* d_out, int out_size)
{
    (void)in_sizes; (void)n_in; (void)out_size;

    const float* temporal = (const float*)d_in[0];
    const float* feature  = (const float*)d_in[1];
    const float* qt_w = (const float*)d_in[2];  const float* qt_b = (const float*)d_in[3];
    const float* kf_w = (const float*)d_in[4];  const float* kf_b = (const float*)d_in[5];
    const float* vf_w = (const float*)d_in[6];  const float* vf_b = (const float*)d_in[7];
    const float* qf_w = (const float*)d_in[8];  const float* qf_b = (const float*)d_in[9];
    const float* kt_w = (const float*)d_in[10]; const float* kt_b = (const float*)d_in[11];
    const float* vt_w = (const float*)d_in[12]; const float* vt_b = (const float*)d_in[13];
    const float* ot_w = (const float*)d_in[14]; const float* ot_b = (const float*)d_in[15];
    const float* of_w = (const float*)d_in[16]; const float* of_b = (const float*)d_in[17];
    const float* fus1_w = (const float*)d_in[18]; const float* fus1_b = (const float*)d_in[19];
    const float* fus2_w = (const float*)d_in[20]; const float* fus2_b = (const float*)d_in[21];
    const float* ln_fus_w = (const float*)d_in[22]; const float* ln_fus_b = (const float*)d_in[23];
    const float* ln_t_w = (const float*)d_in[24]; const float* ln_t_b = (const float*)d_in[25];
    const float* ln_f_w = (const float*)d_in[26]; const float* ln_f_b = (const float*)d_in[27];
    float* out = (float*)d_out;

    bf16 *xt_hi, *xt_lo, *xf_hi, *xf_lo;
    bf16 *q1h, *q1l, *k1h, *k1l, *v1h, *v1l, *q2h, *q2l, *k2h, *k2l, *v2h, *v2l;
    bf16 *a1h, *a1l, *a2h, *a2l, *cat_hi, *cat_lo, *wp_hi, *wp_lo;
    float *t1, *t2;
    cudaGetSymbolAddress((void**)&xt_hi, g_xt_hi); cudaGetSymbolAddress((void**)&xt_lo, g_xt_lo);
    cudaGetSymbolAddress((void**)&xf_hi, g_xf_hi); cudaGetSymbolAddress((void**)&xf_lo, g_xf_lo);
    cudaGetSymbolAddress((void**)&q1h, g_q1h); cudaGetSymbolAddress((void**)&q1l, g_q1l);
    cudaGetSymbolAddress((void**)&k1h, g_k1h); cudaGetSymbolAddress((void**)&k1l, g_k1l);
    cudaGetSymbolAddress((void**)&v1h, g_v1h); cudaGetSymbolAddress((void**)&v1l, g_v1l);
    cudaGetSymbolAddress((void**)&q2h, g_q2h); cudaGetSymbolAddress((void**)&q2l, g_q2l);
    cudaGetSymbolAddress((void**)&k2h, g_k2h); cudaGetSymbolAddress((void**)&k2l, g_k2l);
    cudaGetSymbolAddress((void**)&v2h, g_v2h); cudaGetSymbolAddress((void**)&v2l, g_v2l);
    cudaGetSymbolAddress((void**)&a1h, g_a1h); cudaGetSymbolAddress((void**)&a1l, g_a1l);
    cudaGetSymbolAddress((void**)&a2h, g_a2h); cudaGetSymbolAddress((void**)&a2l, g_a2l);
    cudaGetSymbolAddress((void**)&cat_hi, g_cat_hi); cudaGetSymbolAddress((void**)&cat_lo, g_cat_lo);
    cudaGetSymbolAddress((void**)&wp_hi, g_wp_hi); cudaGetSymbolAddress((void**)&wp_lo, g_wp_lo);
    cudaGetSymbolAddress((void**)&t1, g_t1); cudaGetSymbolAddress((void**)&t2, g_t2);

    cudaFuncSetAttribute(tgemm_qkv, cudaFuncAttributeMaxDynamicSharedMemorySize, TG_SMEM);
    cudaFuncSetAttribute(tgemm_o,   cudaFuncAttributeMaxDynamicSharedMemorySize, TG_SMEM);
    cudaFuncSetAttribute(tgemm<2>,  cudaFuncAttributeMaxDynamicSharedMemorySize, TG_SMEM);
    cudaFuncSetAttribute(tgemm<3>,  cudaFuncAttributeMaxDynamicSharedMemorySize, TG_SMEM);
    cudaFuncSetAttribute(attn_mma,  cudaFuncAttributeMaxDynamicSharedMemorySize, AT_SMEM);

    const int nblk = (M_TOK * D_MODEL) / 1024;
    const dim3 tgrid(1024 / 32, 1024 / 32);
    const dim3 tgrid1(1024 / 32, 2048 / 32);
    const dim3 tblk(32, 8);
    const dim3 qkvgrid(3072 / 128, M_TOK / 128);      // (24, 64)
    const dim3 ggrid(D_MODEL / 128, M_TOK / 128);     // (8, 64)
    const dim3 ogrid(D_MODEL / 128, M_TOK / 128, 2);  // (8, 64, 2)
    const dim3 agrid(SEQ / 128, N_HEADS, 2 * BATCH);  // (16, 16, 8)
    const dim3 lngrid(M_TOK, 2);

    // ---- conversions ----
    split_kernel<<<nblk, 256>>>(temporal, xt_hi, xt_lo);
    split_kernel<<<nblk, 256>>>(feature,  xf_hi, xf_lo);
    wconv<<<tgrid, tblk>>>(qt_w, wp_hi + WOFF_QT, wp_lo + WOFF_QT, 1024, 1024);
    wconv<<<tgrid, tblk>>>(kt_w, wp_hi + WOFF_KT, wp_lo + WOFF_KT, 1024, 1024);
    wconv<<<tgrid, tblk>>>(vt_w, wp_hi + WOFF_VT, wp_lo + WOFF_VT, 1024, 1024);
    wconv<<<tgrid, tblk>>>(qf_w, wp_hi + WOFF_QF, wp_lo + WOFF_QF, 1024, 1024);
    wconv<<<tgrid, tblk>>>(kf_w, wp_hi + WOFF_KF, wp_lo + WOFF_KF, 1024, 1024);
    wconv<<<tgrid, tblk>>>(vf_w, wp_hi + WOFF_VF, wp_lo + WOFF_VF, 1024, 1024);
    wconv<<<tgrid, tblk>>>(ot_w, wp_hi + WOFF_OT, wp_lo + WOFF_OT, 1024, 1024);
    wconv<<<tgrid, tblk>>>(of_w, wp_hi + WOFF_OF, wp_lo + WOFF_OF, 1024, 1024);
    wconv<<<tgrid, tblk>>>(fus2_w, wp_hi + WOFF_F2, wp_lo + WOFF_F2, 1024, 1024);
    wconv<<<tgrid1, tblk>>>(fus1_w, wp_hi + WOFF_F1, wp_lo + WOFF_F1, 2048, 1024);

    // ---- fused QKV projections ----
    tgemm_qkv<<<qkvgrid, 256, TG_SMEM>>>(xt_hi, xt_lo, wp_hi + WOFF_QT, wp_lo + WOFF_QT,
                                         qt_b, kt_b, vt_b,
                                         q1h, q1l, k2h, k2l, v2h, v2l);
    tgemm_qkv<<<qkvgrid, 256, TG_SMEM>>>(xf_hi, xf_lo, wp_hi + WOFF_QF, wp_lo + WOFF_QF,
                                         qf_b, kf_b, vf_b,
                                         q2h, q2l, k1h, k1l, v1h, v1l);

    // ---- both attentions in one launch ----
    attn_mma<<<agrid, 256, AT_SMEM>>>(q1h, q1l, k1h, k1l, v1h, v1l, a1h, a1l,
                                      q2h, q2l, k2h, k2l, v2h, v2l, a2h, a2l);

    // ---- both O-projections in one launch ----
    tgemm_o<<<ogrid, 256, TG_SMEM>>>(a1h, a1l, a2h, a2l, wp_hi + WOFF_OT, wp_lo + WOFF_OT,
                                     ot_b, of_b, temporal, feature, t1, t2);

    // ---- both post-attn LayerNorms in one launch ----
    ln2_kernel<<<lngrid, 256>>>(t1, t2, ln_t_w, ln_t_b, ln_f_w, ln_f_b, cat_hi, cat_lo);

    // ---- fusion MLP ----
    tgemm<2><<<ggrid, 256, TG_SMEM>>>(cat_hi, cat_lo, wp_hi + WOFF_F1, wp_lo + WOFF_F1,
                                      fus1_b, nullptr, q1h, q1l, 2 * D_MODEL);
    tgemm<3><<<ggrid, 256, TG_SMEM>>>(q1h, q1l, wp_hi + WOFF_F2, wp_lo + WOFF_F2,
                                      fus2_b, t1, nullptr, nullptr, D_MODEL);
    ln_final<<<M_TOK, 256>>>(t1, ln_fus_w, ln_fus_b, out);
}